// round 8
// baseline (speedup 1.0000x reference)
#include <cuda_runtime.h>
#include <cuda_bf16.h>

// S4D: out[h,l] = 2*Re( sum_n Ceff[h,n] * exp(dtA[h,n]*l) )
// Per-n real 2-term recurrence y_{l+2}=a*y_{l+1}-b*y_l, packed f32x2 over n-pairs.
// 4-way n-split for single-wave residency: 128 thr = 4 groups x 32 lanes.
// Group g owns 4 n-pairs; lane spans 128 l-values. ~60 live regs -> 7 blocks/SM
// -> all 1024 blocks resident in ONE wave (was 1.38 waves at 5 blocks/SM).
// Per-chunk 4-partial smem reduction; consumer group rotates by chunk.

#define HH      1024
#define NH      32
#define LL      4096
#define THREADS 128
#define NGRP    4
#define LTH     32          // lanes spanning l per group
#define TPT     128         // l-values per thread
#define CH      8           // l per chunk
#define NCH     (TPT / CH)  // 16 chunks
#define NPG     4           // n-pairs per group

#define TWO_PI      6.283185307179586f
#define INV_TWO_PI  0.15915494309189535f

union F2U { float2 f; unsigned long long u; };

__device__ __forceinline__ float2 f2_fma(float2 a, float2 b, float2 c) {
    F2U A, B, C, D; A.f = a; B.f = b; C.f = c;
    asm("fma.rn.f32x2 %0, %1, %2, %3;" : "=l"(D.u) : "l"(A.u), "l"(B.u), "l"(C.u));
    return D.f;
}
__device__ __forceinline__ float2 f2_mul(float2 a, float2 b) {
    F2U A, B, D; A.f = a; B.f = b;
    asm("mul.rn.f32x2 %0, %1, %2;" : "=l"(D.u) : "l"(A.u), "l"(B.u));
    return D.f;
}
__device__ __forceinline__ float2 f2_add(float2 a, float2 b) {
    F2U A, B, D; A.f = a; B.f = b;
    asm("add.rn.f32x2 %0, %1, %2;" : "=l"(D.u) : "l"(A.u), "l"(B.u));
    return D.f;
}

__global__ __launch_bounds__(THREADS, 7)
void s4d_kernel(const float* __restrict__ C_param,     // (H, 32, 2)
                const float* __restrict__ log_dt,      // (H,)
                const float* __restrict__ log_A_real,  // (H, 32)
                const float* __restrict__ A_imag,      // (H, 32)
                float* __restrict__ out)               // (H, L)
{
    __shared__ float s_a[NH], s_nb[NH];
    __shared__ float s_ur[NH], s_ui[NH], s_uwr[NH], s_uwi[NH];
    __shared__ float s_re[NH], s_turn[NH];
    __shared__ float s_red[2][NGRP][LTH][CH];   // 8 KB double-buffered partials

    const int h    = blockIdx.x;
    const int tid  = threadIdx.x;
    const int grp  = tid >> 5;            // 0..3 : which 4 n-pairs (== warp id)
    const int lane = tid & 31;            // which l-range

    // ---- per-(h,n) parameters (one warp; accurate libm ok here) ----
    if (tid < NH) {
        const int n  = tid;
        const int hn = h * NH + n;
        float dt = expf(log_dt[h]);
        float Ar = -expf(log_A_real[hn]);
        float Ai = A_imag[hn];
        float re = Ar * dt;                         // Re(dtA) (<0)
        float im = Ai * dt;                         // Im(dtA)
        float er = expf(re);
        float si, co; sincosf(im, &si, &co);        // |im| small: fast path
        float wr = er * co, wi = er * si;           // w = exp(dtA)
        s_a[n]  = 2.0f * wr;
        s_nb[n] = -fmaf(wr, wr, wi * wi);           // -|w|^2
        // u = 2*C*(w-1)/A
        float numr = wr - 1.0f, numi = wi;
        float invd = 1.0f / fmaf(Ar, Ar, Ai * Ai);
        float tr = (numr * Ar + numi * Ai) * invd;
        float ti = (numi * Ar - numr * Ai) * invd;
        float Cr = C_param[2 * hn + 0];
        float Ci = C_param[2 * hn + 1];
        float ur = 2.0f * (Cr * tr - Ci * ti);
        float ui = 2.0f * (Cr * ti + Ci * tr);
        s_ur[n]  = ur;            s_ui[n]  = ui;
        s_uwr[n] = ur * wr - ui * wi;               // u*w
        s_uwi[n] = ur * wi + ui * wr;
        s_re[n]   = re;
        s_turn[n] = im * INV_TWO_PI;
    }
    __syncthreads();

    // ---- seed recurrence at l0 = lane*TPT for this group's 8 n ----
    const float l0 = (float)(lane * TPT);
    const int   nbase = grp * 2 * NPG;
    float2 Yp[NPG], Yc[NPG], A2[NPG], NB[NPG];

    #pragma unroll
    for (int p = 0; p < NPG; p++) {
        float y0v[2], y1v[2];
        #pragma unroll
        for (int k = 0; k < 2; k++) {
            const int n = nbase + 2 * p + k;
            float amp   = __expf(s_re[n] * l0);     // |w|^{l0}
            float turns = s_turn[n] * l0;
            float frac  = turns - truncf(turns);    // phase mod 1 turn
            float si, co; __sincosf(frac * TWO_PI, &si, &co);
            y0v[k] = amp * (s_ur[n]  * co - s_ui[n]  * si);  // Re(u*w^{l0})
            y1v[k] = amp * (s_uwr[n] * co - s_uwi[n] * si);  // Re(u*w^{l0+1})
        }
        Yp[p] = make_float2(y0v[0], y0v[1]);
        Yc[p] = make_float2(y1v[0], y1v[1]);
        A2[p] = make_float2(s_a[nbase + 2 * p],  s_a[nbase + 2 * p + 1]);
        NB[p] = make_float2(s_nb[nbase + 2 * p], s_nb[nbase + 2 * p + 1]);
    }

    float* orow = out + (size_t)h * LL + lane * TPT;

    // ---- main loop: 16 chunks of 8 l-values ----
    #pragma unroll 1
    for (int c = 0; c < NCH; c++) {
        float2 acc[CH];

        // t-outer / p-inner: consecutive instrs hit independent chains.
        // p=0 peeled to initialize acc (no zero-init).
        #pragma unroll
        for (int t = 0; t < CH; t++) {
            acc[t] = Yp[0];
            {
                float2 tmp = f2_mul(NB[0], Yp[0]);
                float2 y2  = f2_fma(A2[0], Yc[0], tmp);
                Yp[0] = Yc[0]; Yc[0] = y2;
            }
            #pragma unroll
            for (int p = 1; p < NPG; p++) {
                acc[t] = f2_add(acc[t], Yp[p]);
                float2 tmp = f2_mul(NB[p], Yp[p]);
                float2 y2  = f2_fma(A2[p], Yc[p], tmp);
                Yp[p] = Yc[p]; Yc[p] = y2;
            }
        }

        float r[CH];
        #pragma unroll
        for (int t = 0; t < CH; t++) r[t] = acc[t].x + acc[t].y;

        // all groups write their partial; consumer rotates by chunk
        const int buf = c & 1;
        *reinterpret_cast<float4*>(&s_red[buf][grp][lane][0]) =
            make_float4(r[0], r[1], r[2], r[3]);
        *reinterpret_cast<float4*>(&s_red[buf][grp][lane][4]) =
            make_float4(r[4], r[5], r[6], r[7]);
        __syncthreads();

        if (grp == (c & 3)) {
            float4 a0 = *reinterpret_cast<const float4*>(&s_red[buf][0][lane][0]);
            float4 a1 = *reinterpret_cast<const float4*>(&s_red[buf][1][lane][0]);
            float4 a2 = *reinterpret_cast<const float4*>(&s_red[buf][2][lane][0]);
            float4 a3 = *reinterpret_cast<const float4*>(&s_red[buf][3][lane][0]);
            float4 b0 = *reinterpret_cast<const float4*>(&s_red[buf][0][lane][4]);
            float4 b1 = *reinterpret_cast<const float4*>(&s_red[buf][1][lane][4]);
            float4 b2 = *reinterpret_cast<const float4*>(&s_red[buf][2][lane][4]);
            float4 b3 = *reinterpret_cast<const float4*>(&s_red[buf][3][lane][4]);
            float4 o0 = make_float4((a0.x + a1.x) + (a2.x + a3.x),
                                    (a0.y + a1.y) + (a2.y + a3.y),
                                    (a0.z + a1.z) + (a2.z + a3.z),
                                    (a0.w + a1.w) + (a2.w + a3.w));
            float4 o1 = make_float4((b0.x + b1.x) + (b2.x + b3.x),
                                    (b0.y + b1.y) + (b2.y + b3.y),
                                    (b0.z + b1.z) + (b2.z + b3.z),
                                    (b0.w + b1.w) + (b2.w + b3.w));
            *reinterpret_cast<float4*>(orow + c * CH)     = o0;
            *reinterpret_cast<float4*>(orow + c * CH + 4) = o1;
        }
    }
}

extern "C" void kernel_launch(void* const* d_in, const int* in_sizes, int n_in,
                              void* d_out, int out_size) {
    const float* C_param    = (const float*)d_in[0];
    const float* log_dt     = (const float*)d_in[1];
    const float* log_A_real = (const float*)d_in[2];
    const float* A_imag     = (const float*)d_in[3];
    float* out = (float*)d_out;

    s4d_kernel<<<HH, THREADS>>>(C_param, log_dt, log_A_real, A_imag, out);
}

// round 9
// speedup vs baseline: 1.0964x; 1.0964x over previous
#include <cuda_runtime.h>
#include <cuda_bf16.h>

// S4D via Vandermonde factorization: l = 64q + r,
//   out[h, 64q+r] = sum_n Re( u_n * W_n^q * w_n^r ),  W = w^64
// Per block (one h): build P[n][q]=(Re(uW^q),-Im(uW^q)), Q[n][r]=(Re(w^r),Im(w^r))
// in smem, then register-tiled "real-part matmul": acc2 += P2 (.) Q2 — ONE
// packed f32x2 fma per (n, output) vs 1.5 for the recurrence scheme. 32
// independent accumulators per thread -> full ILP, zero barriers in main loop.

#define HH      1024
#define NH      32
#define LL      4096
#define THREADS 128
#define NQ      64          // q dimension (l / 64)
#define NR      64          // r dimension
#define QSTR    68          // smem row stride in float2 (bank-safe, 16B-aligned)
#define TQ      8           // q-tile per thread
#define TR      4           // r-tile per thread

#define TWO_PI      6.283185307179586f
#define INV_TWO_PI  0.15915494309189535f

union F2U { float2 f; unsigned long long u; };

__device__ __forceinline__ float2 f2_fma(float2 a, float2 b, float2 c) {
    F2U A, B, C, D; A.f = a; B.f = b; C.f = c;
    asm("fma.rn.f32x2 %0, %1, %2, %3;" : "=l"(D.u) : "l"(A.u), "l"(B.u), "l"(C.u));
    return D.f;
}

__global__ __launch_bounds__(THREADS)
void s4d_kernel(const float* __restrict__ C_param,     // (H, 32, 2)
                const float* __restrict__ log_dt,      // (H,)
                const float* __restrict__ log_A_real,  // (H, 32)
                const float* __restrict__ A_imag,      // (H, 32)
                float* __restrict__ out)               // (H, L)
{
    __shared__ float2 P_s[NH][QSTR];      // (Re(u*W^q), -Im(u*W^q))
    __shared__ float2 Q_s[NH][QSTR];      // (Re(w^r),  Im(w^r))
    __shared__ float s_re[NH], s_turn[NH], s_wr[NH], s_wi[NH];
    __shared__ float s_ur[NH], s_ui[NH], s_Wr[NH], s_Wi[NH];

    const int h   = blockIdx.x;
    const int tid = threadIdx.x;

    // ---- per-(h,n) parameters (one warp; accurate libm) ----
    if (tid < NH) {
        const int n  = tid;
        const int hn = h * NH + n;
        float dt = expf(log_dt[h]);
        float Ar = -expf(log_A_real[hn]);
        float Ai = A_imag[hn];
        float re = Ar * dt;                          // Re(dtA) (<0)
        float im = Ai * dt;                          // Im(dtA)
        float er = expf(re);
        float si, co; sincosf(im, &si, &co);
        float wr = er * co, wi = er * si;            // w = exp(dtA)
        // u = 2*C*(w-1)/A
        float numr = wr - 1.0f, numi = wi;
        float invd = 1.0f / fmaf(Ar, Ar, Ai * Ai);
        float tr = (numr * Ar + numi * Ai) * invd;
        float ti = (numi * Ar - numr * Ai) * invd;
        float Cr = C_param[2 * hn + 0];
        float Ci = C_param[2 * hn + 1];
        float ur = 2.0f * (Cr * tr - Ci * ti);
        float ui = 2.0f * (Cr * ti + Ci * tr);
        float turn = im * INV_TWO_PI;
        // W = w^64 via turn trick
        float amp64 = expf(64.0f * re);
        float t64   = turn * 64.0f;
        float f64   = t64 - truncf(t64);
        float s64, c64; __sincosf(f64 * TWO_PI, &s64, &c64);
        s_re[n]   = re;   s_turn[n] = turn;
        s_wr[n]   = wr;   s_wi[n]   = wi;
        s_ur[n]   = ur;   s_ui[n]   = ui;
        s_Wr[n]   = amp64 * c64;  s_Wi[n] = amp64 * s64;
    }
    __syncthreads();

    // ---- generate P and Q tiles: thread (n = tid>>2, j = tid&3) ----
    {
        const int gn = tid >> 2;
        const int gj = tid & 3;
        const float re = s_re[gn], tn = s_turn[gn];

        // Q[n][r] = w^r for r = 16j .. 16j+15
        {
            const float wr = s_wr[gn], wi = s_wi[gn];
            float r0f  = (float)(16 * gj);
            float amp  = __expf(re * r0f);
            float turns = tn * r0f;
            float frac  = turns - truncf(turns);
            float si, co; __sincosf(frac * TWO_PI, &si, &co);
            float zr = amp * co, zi = amp * si;
            #pragma unroll
            for (int i = 0; i < 16; i++) {
                Q_s[gn][16 * gj + i] = make_float2(zr, zi);
                float nzr = zr * wr - zi * wi;
                float nzi = zr * wi + zi * wr;
                zr = nzr; zi = nzi;
            }
        }
        // P[n][q] = u * W^q for q = 16j .. 16j+15  (stored as (pr, -pi))
        {
            const float Wr = s_Wr[gn], Wi = s_Wi[gn];
            const float ur = s_ur[gn], ui = s_ui[gn];
            float l0f  = (float)(1024 * gj);          // 64 * 16j
            float amp  = __expf(re * l0f);
            float turns = tn * l0f;
            float frac  = turns - truncf(turns);
            float si, co; __sincosf(frac * TWO_PI, &si, &co);
            float zr = amp * co, zi = amp * si;       // w^{64*16j}
            float pr = ur * zr - ui * zi;
            float pi = ur * zi + ui * zr;
            #pragma unroll
            for (int i = 0; i < 16; i++) {
                P_s[gn][16 * gj + i] = make_float2(pr, -pi);
                float npr = pr * Wr - pi * Wi;
                float npi = pr * Wi + pi * Wr;
                pr = npr; pi = npi;
            }
        }
    }
    __syncthreads();

    // ---- main: register-tiled real-part matmul, zero barriers ----
    const int q0 = (tid >> 4) << 3;     // 8 q-tiles of 8
    const int r0 = (tid & 15) << 2;     // 16 r-tiles of 4

    float2 acc[TQ][TR];
    #pragma unroll
    for (int qi = 0; qi < TQ; qi++)
        #pragma unroll
        for (int ri = 0; ri < TR; ri++)
            acc[qi][ri] = make_float2(0.0f, 0.0f);

    #pragma unroll 4
    for (int n = 0; n < NH; n++) {
        float2 Pv[TQ], Qv[TR];
        #pragma unroll
        for (int m = 0; m < TQ; m += 2) {
            float4 t = *reinterpret_cast<const float4*>(&P_s[n][q0 + m]);
            Pv[m]     = make_float2(t.x, t.y);
            Pv[m + 1] = make_float2(t.z, t.w);
        }
        #pragma unroll
        for (int m = 0; m < TR; m += 2) {
            float4 t = *reinterpret_cast<const float4*>(&Q_s[n][r0 + m]);
            Qv[m]     = make_float2(t.x, t.y);
            Qv[m + 1] = make_float2(t.z, t.w);
        }
        #pragma unroll
        for (int qi = 0; qi < TQ; qi++)
            #pragma unroll
            for (int ri = 0; ri < TR; ri++)
                acc[qi][ri] = f2_fma(Pv[qi], Qv[ri], acc[qi][ri]);
    }

    // ---- epilogue: out[h, 64*(q0+qi) + r0 + ri] = acc.x + acc.y ----
    float* orow = out + (size_t)h * LL + r0;
    #pragma unroll
    for (int qi = 0; qi < TQ; qi++) {
        float4 o = make_float4(acc[qi][0].x + acc[qi][0].y,
                               acc[qi][1].x + acc[qi][1].y,
                               acc[qi][2].x + acc[qi][2].y,
                               acc[qi][3].x + acc[qi][3].y);
        *reinterpret_cast<float4*>(orow + (q0 + qi) * NR) = o;
    }
}

extern "C" void kernel_launch(void* const* d_in, const int* in_sizes, int n_in,
                              void* d_out, int out_size) {
    const float* C_param    = (const float*)d_in[0];
    const float* log_dt     = (const float*)d_in[1];
    const float* log_A_real = (const float*)d_in[2];
    const float* A_imag     = (const float*)d_in[3];
    float* out = (float*)d_out;

    s4d_kernel<<<HH, THREADS>>>(C_param, log_dt, log_A_real, A_imag, out);
}